// round 7
// baseline (speedup 1.0000x reference)
#include <cuda_runtime.h>
#include <cuda_fp16.h>
#include <math.h>
#include <stdint.h>

// ---------------- problem constants ----------------
#define BB 2
#define LL 2048
#define HH 1536
#define II 3072
#define NN 16
#define RR 96
#define MTOT 4096
#define E2 6144
#define PP 128
#define SPLITK 8

// ---------------- fp32 scratch ----------------
__device__ __align__(256) float g_ssmp[(size_t)MTOT * PP];
__device__ __align__(256) float g_part[SPLITK * (size_t)MTOT * PP];

// ---------------- fp16 scratch ----------------
__device__ __align__(256) __half g_proj16[(size_t)MTOT * E2];   // in_proj out (x | gate)
__device__ __align__(256) __half g_delta16[(size_t)MTOT * II];  // softplus(dt+bias)
__device__ __align__(256) __half g_hs16[(size_t)MTOT * HH];
__device__ __align__(256) __half g_Win16[(size_t)E2 * HH];
__device__ __align__(256) __half g_x16[(size_t)MTOT * II];
__device__ __align__(256) __half g_Wx16[(size_t)PP * II];
__device__ __align__(256) __half g_sp16[(size_t)MTOT * PP];
__device__ __align__(256) __half g_Wdt16[(size_t)II * PP];      // K padded 96->128
__device__ __align__(256) __half g_y16[(size_t)MTOT * II];
__device__ __align__(256) __half g_Wout16[(size_t)HH * II];

// ---------------- helpers ----------------
__device__ __forceinline__ float fast_ex2(float x) {
    float r; asm("ex2.approx.f32 %0, %1;" : "=f"(r) : "f"(x)); return r;
}
__device__ __forceinline__ uint32_t smem_u32(const void* p) {
    return (uint32_t)__cvta_generic_to_shared(p);
}
__device__ __forceinline__ void cp16(void* dst_smem, const void* src_gmem) {
    unsigned d = smem_u32(dst_smem);
    asm volatile("cp.async.cg.shared.global [%0], [%1], 16;" :: "r"(d), "l"(src_gmem));
}
__device__ __forceinline__ void cp_commit() { asm volatile("cp.async.commit_group;"); }
__device__ __forceinline__ void cp_wait1() { asm volatile("cp.async.wait_group 1;" ::: "memory"); }
__device__ __forceinline__ void cp_wait0() { asm volatile("cp.async.wait_group 0;" ::: "memory"); }

__device__ __forceinline__ void ldsm4(uint32_t& r0, uint32_t& r1, uint32_t& r2, uint32_t& r3,
                                      uint32_t addr) {
    asm volatile("ldmatrix.sync.aligned.m8n8.x4.shared.b16 {%0,%1,%2,%3}, [%4];"
                 : "=r"(r0), "=r"(r1), "=r"(r2), "=r"(r3) : "r"(addr));
}
__device__ __forceinline__ void mma16816(float* d, const uint32_t* a, const uint32_t* b) {
    asm volatile("mma.sync.aligned.m16n8k16.row.col.f32.f16.f16.f32 "
                 "{%0,%1,%2,%3}, {%4,%5,%6,%7}, {%8,%9}, {%0,%1,%2,%3};"
                 : "+f"(d[0]), "+f"(d[1]), "+f"(d[2]), "+f"(d[3])
                 : "r"(a[0]), "r"(a[1]), "r"(a[2]), "r"(a[3]), "r"(b[0]), "r"(b[1]));
}
__device__ __forceinline__ uint32_t pack2(float a, float b) {
    __half2 h = __floats2half2_rn(a, b);
    return *(uint32_t*)&h;
}

// ============================================================================
// fp16 single-pass GEMM: C[M,N] = A[M,K] * B[N,K]^T, fp32 accum.
// 128x128 CTA tile, BK=64, 3-stage cp.async (96KB -> 2 CTAs/SM),
// 8 warps (2m x 4n), warp 64x32. Split-K via blockIdx.z.
// EPI==1: softplus(C + bias[col]).  OUT16: write __half.
// ============================================================================
#define TILE_B 16384
#define STAGE_B (2 * TILE_B)
#define GEMM_SMEM (3 * STAGE_B)

template <int EPI, int OUT16>
__global__ __launch_bounds__(256)
void gemm_mma(const __half* __restrict__ A, const __half* __restrict__ B,
              int K, void* __restrict__ Cv, int ldc,
              size_t c_part_stride, const float* __restrict__ bias) {
    extern __shared__ char smem[];
    const int tid = threadIdx.x;
    const int lane = tid & 31;
    const int wid = tid >> 5;
    const int m0 = blockIdx.y * 128;
    const int n0 = blockIdx.x * 128;
    const int wm = (wid & 1) * 64;
    const int wn = (wid >> 1) * 32;
    const int ncz = (K >> 6) / gridDim.z;
    const int c0 = blockIdx.z * ncz;

    float acc[4][4][4] = {};

    auto issue = [&](int lc) {
        char* st = smem + (lc % 3) * STAGE_B;
        const int k0 = (c0 + lc) << 6;
#pragma unroll
        for (int rep = 0; rep < 4; rep++) {
            int idx = tid + rep * 256;
            int r = idx >> 3;
            int cc = idx & 7;
            uint32_t so = (uint32_t)(r * 128 + ((cc ^ (r & 7)) * 16));
            cp16(st + so, A + (size_t)(m0 + r) * K + k0 + cc * 8);
            cp16(st + TILE_B + so, B + (size_t)(n0 + r) * K + k0 + cc * 8);
        }
    };

    issue(0); cp_commit();
    if (ncz > 1) issue(1);
    cp_commit();

    const int a_row = lane & 15;
    const int a_kh = lane >> 4;
    const int b_nr = (lane & 7) + ((lane >> 4) << 3);
    const int b_kh = (lane >> 3) & 1;

    for (int lc = 0; lc < ncz; lc++) {
        cp_wait1();
        __syncthreads();
        if (lc + 2 < ncz) issue(lc + 2);
        cp_commit();

        const uint32_t sA = smem_u32(smem + (lc % 3) * STAGE_B);
        const uint32_t sB = sA + TILE_B;

#pragma unroll
        for (int kc = 0; kc < 8; kc += 2) {
            uint32_t bf[4][2];
#pragma unroll
            for (int jj = 0; jj < 2; jj++) {
                int r = wn + b_nr + jj * 16;
                uint32_t off = (uint32_t)(r * 128 + (((kc + b_kh) ^ (r & 7)) * 16));
                uint32_t t0, t1, t2, t3;
                ldsm4(t0, t1, t2, t3, sB + off);
                bf[jj * 2][0] = t0; bf[jj * 2][1] = t1;
                bf[jj * 2 + 1][0] = t2; bf[jj * 2 + 1][1] = t3;
            }
#pragma unroll
            for (int i = 0; i < 4; i++) {
                int r = wm + i * 16 + a_row;
                uint32_t off = (uint32_t)(r * 128 + (((kc + a_kh) ^ (r & 7)) * 16));
                uint32_t af[4];
                ldsm4(af[0], af[1], af[2], af[3], sA + off);
#pragma unroll
                for (int j = 0; j < 4; j++)
                    mma16816(acc[i][j], af, bf[j]);
            }
        }
        __syncthreads();
    }

    // epilogue
    const int quad = lane >> 2;
    const int tq = lane & 3;
#pragma unroll
    for (int i = 0; i < 4; i++) {
#pragma unroll
        for (int j = 0; j < 4; j++) {
            int r0 = m0 + wm + i * 16 + quad;
            int cc = n0 + wn + j * 8 + tq * 2;
            float v0 = acc[i][j][0], v1 = acc[i][j][1];
            float v2 = acc[i][j][2], v3 = acc[i][j][3];
            if (EPI == 1) {
                float b0 = bias[cc], b1 = bias[cc + 1];
                v0 += b0; v1 += b1; v2 += b0; v3 += b1;
                v0 = (v0 > 20.0f) ? v0 : log1pf(__expf(v0));
                v1 = (v1 > 20.0f) ? v1 : log1pf(__expf(v1));
                v2 = (v2 > 20.0f) ? v2 : log1pf(__expf(v2));
                v3 = (v3 > 20.0f) ? v3 : log1pf(__expf(v3));
            }
            if (OUT16) {
                __half* C16 = (__half*)Cv;
                *(__half2*)(C16 + (size_t)r0 * ldc + cc) = __floats2half2_rn(v0, v1);
                *(__half2*)(C16 + (size_t)(r0 + 8) * ldc + cc) = __floats2half2_rn(v2, v3);
            } else {
                float* C = (float*)Cv + (size_t)blockIdx.z * c_part_stride;
                *(float2*)(C + (size_t)r0 * ldc + cc) = make_float2(v0, v1);
                *(float2*)(C + (size_t)(r0 + 8) * ldc + cc) = make_float2(v2, v3);
            }
        }
    }
}

// ============================================================================
// conversion kernels
// ============================================================================
__global__ void convert16_kernel(const float4* __restrict__ src,
                                 uint2* __restrict__ dst, int n4) {
    int i = blockIdx.x * blockDim.x + threadIdx.x;
    if (i >= n4) return;
    float4 v = src[i];
    uint2 o;
    o.x = pack2(v.x, v.y);
    o.y = pack2(v.z, v.w);
    dst[i] = o;
}

__global__ void convert_wdt_kernel(const float* __restrict__ src,
                                   uint2* __restrict__ dst) {
    int idx = blockIdx.x * blockDim.x + threadIdx.x;
    if (idx >= II * 32) return;
    int k4 = (idx & 31) * 4;
    int i = idx >> 5;
    float v[4];
#pragma unroll
    for (int t = 0; t < 4; t++)
        v[t] = (k4 + t < RR) ? src[i * RR + k4 + t] : 0.0f;
    uint2 o;
    o.x = pack2(v[0], v[1]);
    o.y = pack2(v[2], v[3]);
    dst[idx] = o;
}

__global__ void reduce_ssmp_kernel() {
    int idx = blockIdx.x * blockDim.x + threadIdx.x;
    if (idx >= MTOT * PP / 4) return;
    const size_t s4 = (size_t)MTOT * PP / 4;
    const float4* p = (const float4*)g_part;
    float4 a = p[idx];
#pragma unroll
    for (int z = 1; z < SPLITK; z++) {
        float4 b = p[z * s4 + idx];
        a.x += b.x; a.y += b.y; a.z += b.z; a.w += b.w;
    }
    ((float4*)g_ssmp)[idx] = a;
    uint2 o; o.x = pack2(a.x, a.y); o.y = pack2(a.z, a.w);
    ((uint2*)g_sp16)[idx] = o;
}

// ============================================================================
// causal depthwise conv1d (K=4) + SiLU; fp16 in/out, 2 channels x 4 steps/thread
// ============================================================================
__global__ void conv_silu_kernel(const float* __restrict__ conv_w,
                                 const float* __restrict__ conv_b) {
    int idx = blockIdx.x * blockDim.x + threadIdx.x;
    if (idx >= (MTOT / 4) * (II / 2)) return;
    const int i2 = idx % (II / 2);
    const int t = idx / (II / 2);
    const int m0 = t * 4;
    const int l0 = m0 & (LL - 1);
    const int i = i2 * 2;

    float wa[4], wb[4];
#pragma unroll
    for (int j = 0; j < 4; j++) {
        wa[j] = conv_w[i * 4 + j];
        wb[j] = conv_w[(i + 1) * 4 + j];
    }
    const float cba = conv_b[i], cbb = conv_b[i + 1];

    float va[7], vb[7];
#pragma unroll
    for (int j = 0; j < 7; j++) {
        int l = l0 - 3 + j;
        if (l >= 0) {
            __half2 h = *(const __half2*)&g_proj16[(size_t)(m0 - 3 + j) * E2 + i];
            float2 f = __half22float2(h);
            va[j] = f.x; vb[j] = f.y;
        } else {
            va[j] = 0.0f; vb[j] = 0.0f;
        }
    }
#pragma unroll
    for (int s = 0; s < 4; s++) {
        float aa = cba, ab = cbb;
#pragma unroll
        for (int j = 0; j < 4; j++) {
            aa = fmaf(va[s + j], wa[j], aa);
            ab = fmaf(vb[s + j], wb[j], ab);
        }
        float oa = aa / (1.0f + __expf(-aa));
        float ob = ab / (1.0f + __expf(-ab));
        *(__half2*)&g_x16[(size_t)(m0 + s) * II + i] = __floats2half2_rn(oa, ob);
    }
}

// ============================================================================
// Selective scan + D-skip + gate*silu(gate); fp16 streams via cp.async.
// ============================================================================
#define SCH 32
#define NCHUNK (LL / SCH)

__global__ __launch_bounds__(128)
void scan_kernel(const float* __restrict__ Amat, const float* __restrict__ Dvec) {
    __shared__ __align__(16) __half sD16[2][SCH * 32];
    __shared__ __align__(16) __half sX16[2][SCH * 32];
    __shared__ __align__(16) __half sG16[2][SCH * 32];
    __shared__ __align__(16) float sBC[2][SCH * 32];
    __shared__ __align__(16) float sY[SCH * 32];

    const int tid = threadIdx.x;
    const int blk = blockIdx.x;
    const int b = blk / 96;
    const int ibase = (blk % 96) * 32;
    const int q = tid & 3;
    const int c = tid >> 2;
    const int i = ibase + c;
    const int mbase = b * LL;

    float a2[4];
#pragma unroll
    for (int n = 0; n < 4; n++)
        a2[n] = Amat[i * NN + q * 4 + n] * 1.4426950408889634f;
    const float dv = Dvec[i];
    float st[4] = {0.0f, 0.0f, 0.0f, 0.0f};

    auto issue = [&](int buf, int ch) {
        const int m0 = mbase + ch * SCH;
        // fp16 tensors: 32 steps x 32 ch x 2B = 2048B = 128 x 16B chunks, 1/thread
        {
            int l = tid >> 2;
            int c8 = (tid & 3) * 8;
            int m = m0 + l;
            cp16(&sD16[buf][l * 32 + c8], &g_delta16[(size_t)m * II + ibase + c8]);
            cp16(&sX16[buf][l * 32 + c8], &g_x16[(size_t)m * II + ibase + c8]);
            cp16(&sG16[buf][l * 32 + c8], &g_proj16[(size_t)m * E2 + II + ibase + c8]);
        }
        // BC fp32: 32 steps x 32 floats = 4096B = 256 x 16B chunks, 2/thread
#pragma unroll
        for (int k2 = 0; k2 < 2; k2++) {
            int f = tid + k2 * 128;
            int l = f >> 3;
            int c4 = (f & 7) * 4;
            int m = m0 + l;
            cp16(&sBC[buf][l * 32 + c4], &g_ssmp[(size_t)m * PP + RR + c4]);
        }
    };

    issue(0, 0);
    cp_commit();

    for (int ch = 0; ch < NCHUNK; ch++) {
        const int cur = ch & 1;
        if (ch + 1 < NCHUNK) {
            issue(1 - cur, ch + 1);
            cp_commit();
            cp_wait1();
        } else {
            cp_wait0();
        }
        __syncthreads();

        const int m0 = mbase + ch * SCH;
#pragma unroll 4
        for (int l = 0; l < SCH; l++) {
            const float delta = __half2float(sD16[cur][l * 32 + c]);
            const float xv = __half2float(sX16[cur][l * 32 + c]);
            const float du = delta * xv;
            const float4 Bv = *(const float4*)&sBC[cur][l * 32 + q * 4];
            const float4 Cv = *(const float4*)&sBC[cur][l * 32 + 16 + q * 4];
            float dA0 = fast_ex2(delta * a2[0]);
            float dA1 = fast_ex2(delta * a2[1]);
            float dA2 = fast_ex2(delta * a2[2]);
            float dA3 = fast_ex2(delta * a2[3]);
            st[0] = fmaf(st[0], dA0, du * Bv.x);
            st[1] = fmaf(st[1], dA1, du * Bv.y);
            st[2] = fmaf(st[2], dA2, du * Bv.z);
            st[3] = fmaf(st[3], dA3, du * Bv.w);
            float y = st[0] * Cv.x + st[1] * Cv.y + st[2] * Cv.z + st[3] * Cv.w;
            y += __shfl_xor_sync(0xffffffffu, y, 1);
            y += __shfl_xor_sync(0xffffffffu, y, 2);
            if (q == 0) {
                const float g = __half2float(sG16[cur][l * 32 + c]);
                const float sg = g / (1.0f + __expf(-g));
                sY[l * 32 + c] = (y + xv * dv) * sg;
            }
        }
        __syncthreads();

#pragma unroll
        for (int k2 = 0; k2 < 4; k2++) {
            int f = tid + k2 * 128;
            int l = f >> 4;
            int c2 = (f & 15) * 2;
            __half2 p = __floats2half2_rn(sY[l * 32 + c2], sY[l * 32 + c2 + 1]);
            *(__half2*)&g_y16[(size_t)(m0 + l) * II + ibase + c2] = p;
        }
    }
}

// ============================================================================
// kernel_launch
// ============================================================================
extern "C" void kernel_launch(void* const* d_in, const int* in_sizes, int n_in,
                              void* d_out, int out_size) {
    const float* hs      = (const float*)d_in[0];
    const float* W_in    = (const float*)d_in[1];
    const float* conv_w  = (const float*)d_in[2];
    const float* conv_b  = (const float*)d_in[3];
    const float* W_x     = (const float*)d_in[4];
    const float* W_dt    = (const float*)d_in[5];
    const float* dt_bias = (const float*)d_in[6];
    const float* Amat    = (const float*)d_in[7];
    const float* Dvec    = (const float*)d_in[8];
    const float* W_out   = (const float*)d_in[9];
    float* out = (float*)d_out;

    float *part;
    cudaGetSymbolAddress((void**)&part, g_part);
    __half *proj16, *delta16, *hs16, *Win16, *x16, *Wx16, *sp16, *Wdt16, *y16, *Wout16;
    cudaGetSymbolAddress((void**)&proj16, g_proj16);
    cudaGetSymbolAddress((void**)&delta16, g_delta16);
    cudaGetSymbolAddress((void**)&hs16, g_hs16);
    cudaGetSymbolAddress((void**)&Win16, g_Win16);
    cudaGetSymbolAddress((void**)&x16, g_x16);
    cudaGetSymbolAddress((void**)&Wx16, g_Wx16);
    cudaGetSymbolAddress((void**)&sp16, g_sp16);
    cudaGetSymbolAddress((void**)&Wdt16, g_Wdt16);
    cudaGetSymbolAddress((void**)&y16, g_y16);
    cudaGetSymbolAddress((void**)&Wout16, g_Wout16);

    cudaFuncSetAttribute((const void*)gemm_mma<0, 0>, cudaFuncAttributeMaxDynamicSharedMemorySize, GEMM_SMEM);
    cudaFuncSetAttribute((const void*)gemm_mma<0, 1>, cudaFuncAttributeMaxDynamicSharedMemorySize, GEMM_SMEM);
    cudaFuncSetAttribute((const void*)gemm_mma<1, 1>, cudaFuncAttributeMaxDynamicSharedMemorySize, GEMM_SMEM);

    // conversions
    {
        int n4;
        n4 = MTOT * HH / 4;
        convert16_kernel<<<(n4 + 255) / 256, 256>>>((const float4*)hs, (uint2*)hs16, n4);
        n4 = E2 * HH / 4;
        convert16_kernel<<<(n4 + 255) / 256, 256>>>((const float4*)W_in, (uint2*)Win16, n4);
        n4 = PP * II / 4;
        convert16_kernel<<<(n4 + 255) / 256, 256>>>((const float4*)W_x, (uint2*)Wx16, n4);
        n4 = HH * II / 4;
        convert16_kernel<<<(n4 + 255) / 256, 256>>>((const float4*)W_out, (uint2*)Wout16, n4);
        n4 = II * 32;
        convert_wdt_kernel<<<(n4 + 255) / 256, 256>>>(W_dt, (uint2*)Wdt16);
    }

    // 1) in_proj -> fp16 proj (x | gate)  (K=1536)
    gemm_mma<0, 1><<<dim3(E2 / 128, MTOT / 128, 1), 256, GEMM_SMEM>>>(
        hs16, Win16, HH, proj16, E2, 0, nullptr);

    // 2) conv + SiLU -> g_x16
    {
        int total = (MTOT / 4) * (II / 2);
        conv_silu_kernel<<<(total + 255) / 256, 256>>>(conv_w, conv_b);
    }

    // 3) x_proj split-K(8) -> fp32 partials  (K=3072)
    gemm_mma<0, 0><<<dim3(1, MTOT / 128, SPLITK), 256, GEMM_SMEM>>>(
        x16, Wx16, II, part, PP, (size_t)MTOT * PP, nullptr);
    {
        int n4 = MTOT * PP / 4;
        reduce_ssmp_kernel<<<(n4 + 255) / 256, 256>>>();
    }

    // 4) dt_proj + softplus -> fp16 delta  (K=128 padded)
    gemm_mma<1, 1><<<dim3(II / 128, MTOT / 128, 1), 256, GEMM_SMEM>>>(
        sp16, Wdt16, 128, delta16, II, 0, dt_bias);

    // 5) scan -> y fp16
    scan_kernel<<<192, 128>>>(Amat, Dvec);

    // 6) out_proj -> fp32 out  (K=3072)
    gemm_mma<0, 0><<<dim3(HH / 128, MTOT / 128, 1), 256, GEMM_SMEM>>>(
        y16, Wout16, II, out, HH, 0, nullptr);
}

// round 9
// speedup vs baseline: 1.0140x; 1.0140x over previous
#include <cuda_runtime.h>
#include <cuda_fp16.h>
#include <math.h>
#include <stdint.h>

// ---------------- problem constants ----------------
#define BB 2
#define LL 2048
#define HH 1536
#define II 3072
#define NN 16
#define RR 96
#define MTOT 4096
#define E2 6144
#define PP 128
#define SPLITK 8

// ---------------- fp32 scratch ----------------
__device__ __align__(256) float g_proj[(size_t)MTOT * E2];
__device__ __align__(256) float g_x[(size_t)MTOT * II];
__device__ __align__(256) float g_ssmp[(size_t)MTOT * PP];
__device__ __align__(256) float g_delta[(size_t)MTOT * II];
__device__ __align__(256) float g_part[SPLITK * (size_t)MTOT * PP];

// ---------------- fp16 scratch ----------------
__device__ __align__(256) __half g_hs16[(size_t)MTOT * HH];
__device__ __align__(256) __half g_Win16[(size_t)E2 * HH];
__device__ __align__(256) __half g_x16[(size_t)MTOT * II];
__device__ __align__(256) __half g_Wx16[(size_t)PP * II];
__device__ __align__(256) __half g_sp16[(size_t)MTOT * PP];
__device__ __align__(256) __half g_Wdt16[(size_t)II * PP];   // K padded 96->128
__device__ __align__(256) __half g_y16[(size_t)MTOT * II];
__device__ __align__(256) __half g_Wout16[(size_t)HH * II];

// ---------------- helpers ----------------
__device__ __forceinline__ float fast_ex2(float x) {
    float r; asm("ex2.approx.f32 %0, %1;" : "=f"(r) : "f"(x)); return r;
}
__device__ __forceinline__ uint32_t smem_u32(const void* p) {
    return (uint32_t)__cvta_generic_to_shared(p);
}
__device__ __forceinline__ void cp16(void* dst_smem, const void* src_gmem) {
    unsigned d = smem_u32(dst_smem);
    asm volatile("cp.async.cg.shared.global [%0], [%1], 16;" :: "r"(d), "l"(src_gmem));
}
__device__ __forceinline__ void cp_commit() { asm volatile("cp.async.commit_group;"); }
__device__ __forceinline__ void cp_wait1() { asm volatile("cp.async.wait_group 1;" ::: "memory"); }
__device__ __forceinline__ void cp_wait0() { asm volatile("cp.async.wait_group 0;" ::: "memory"); }

__device__ __forceinline__ void ldsm4(uint32_t& r0, uint32_t& r1, uint32_t& r2, uint32_t& r3,
                                      uint32_t addr) {
    asm volatile("ldmatrix.sync.aligned.m8n8.x4.shared.b16 {%0,%1,%2,%3}, [%4];"
                 : "=r"(r0), "=r"(r1), "=r"(r2), "=r"(r3) : "r"(addr));
}
__device__ __forceinline__ void mma16816(float* d, const uint32_t* a, const uint32_t* b) {
    asm volatile("mma.sync.aligned.m16n8k16.row.col.f32.f16.f16.f32 "
                 "{%0,%1,%2,%3}, {%4,%5,%6,%7}, {%8,%9}, {%0,%1,%2,%3};"
                 : "+f"(d[0]), "+f"(d[1]), "+f"(d[2]), "+f"(d[3])
                 : "r"(a[0]), "r"(a[1]), "r"(a[2]), "r"(a[3]), "r"(b[0]), "r"(b[1]));
}
__device__ __forceinline__ uint32_t pack2(float a, float b) {
    __half2 h = __floats2half2_rn(a, b);
    return *(uint32_t*)&h;
}

// ============================================================================
// fp16 single-pass GEMM: C[M,N] = A[M,K] * B[N,K]^T, fp32 accum.
// 128x128 CTA tile, BK=64, 3-stage cp.async, 8 warps (2m x 4n), warp 64x32.
// __launch_bounds__(256, 2): force 2 CTAs/SM (regs <= 128, smem 2x96KB).
// Split-K via blockIdx.z. EPI==1: softplus(C + bias[col]).
// ============================================================================
#define TILE_B 16384
#define STAGE_B (2 * TILE_B)
#define GEMM_SMEM (3 * STAGE_B)

template <int EPI>
__global__ __launch_bounds__(256, 2)
void gemm_mma(const __half* __restrict__ A, const __half* __restrict__ B,
              int K, float* __restrict__ C, int ldc,
              size_t c_part_stride, const float* __restrict__ bias) {
    extern __shared__ char smem[];
    const int tid = threadIdx.x;
    const int lane = tid & 31;
    const int wid = tid >> 5;
    const int m0 = blockIdx.y * 128;
    const int n0 = blockIdx.x * 128;
    const int wm = (wid & 1) * 64;
    const int wn = (wid >> 1) * 32;
    const int ncz = (K >> 6) / gridDim.z;
    const int c0 = blockIdx.z * ncz;
    C += (size_t)blockIdx.z * c_part_stride;

    float acc[4][4][4] = {};

    auto issue = [&](int lc) {
        char* st = smem + (lc % 3) * STAGE_B;
        const int k0 = (c0 + lc) << 6;
#pragma unroll
        for (int rep = 0; rep < 4; rep++) {
            int idx = tid + rep * 256;
            int r = idx >> 3;
            int cc = idx & 7;
            uint32_t so = (uint32_t)(r * 128 + ((cc ^ (r & 7)) * 16));
            cp16(st + so, A + (size_t)(m0 + r) * K + k0 + cc * 8);
            cp16(st + TILE_B + so, B + (size_t)(n0 + r) * K + k0 + cc * 8);
        }
    };

    issue(0); cp_commit();
    if (ncz > 1) issue(1);
    cp_commit();

    const int a_row = lane & 15;
    const int a_kh = lane >> 4;
    const int b_nr = (lane & 7) + ((lane >> 4) << 3);
    const int b_kh = (lane >> 3) & 1;

    for (int lc = 0; lc < ncz; lc++) {
        cp_wait1();
        __syncthreads();
        if (lc + 2 < ncz) issue(lc + 2);
        cp_commit();

        const uint32_t sA = smem_u32(smem + (lc % 3) * STAGE_B);
        const uint32_t sB = sA + TILE_B;

#pragma unroll
        for (int kc = 0; kc < 8; kc += 2) {
            // hoist ALL fragment loads for this k-step before the MMAs
            uint32_t bf[4][2];
            uint32_t af[4][4];
#pragma unroll
            for (int jj = 0; jj < 2; jj++) {
                int r = wn + b_nr + jj * 16;
                uint32_t off = (uint32_t)(r * 128 + (((kc + b_kh) ^ (r & 7)) * 16));
                uint32_t t0, t1, t2, t3;
                ldsm4(t0, t1, t2, t3, sB + off);
                bf[jj * 2][0] = t0; bf[jj * 2][1] = t1;
                bf[jj * 2 + 1][0] = t2; bf[jj * 2 + 1][1] = t3;
            }
#pragma unroll
            for (int i = 0; i < 4; i++) {
                int r = wm + i * 16 + a_row;
                uint32_t off = (uint32_t)(r * 128 + (((kc + a_kh) ^ (r & 7)) * 16));
                ldsm4(af[i][0], af[i][1], af[i][2], af[i][3], sA + off);
            }
#pragma unroll
            for (int i = 0; i < 4; i++)
#pragma unroll
                for (int j = 0; j < 4; j++)
                    mma16816(acc[i][j], af[i], bf[j]);
        }
        // no trailing __syncthreads: next iteration's cp_wait1+__syncthreads
        // orders stage reuse (issue(lc+3) can only start after all warps
        // finished reading stage lc%3).
    }

    // epilogue
    const int quad = lane >> 2;
    const int tq = lane & 3;
#pragma unroll
    for (int i = 0; i < 4; i++) {
#pragma unroll
        for (int j = 0; j < 4; j++) {
            int r0 = m0 + wm + i * 16 + quad;
            int cc = n0 + wn + j * 8 + tq * 2;
            float v0 = acc[i][j][0], v1 = acc[i][j][1];
            float v2 = acc[i][j][2], v3 = acc[i][j][3];
            if (EPI == 1) {
                float b0 = bias[cc], b1 = bias[cc + 1];
                v0 += b0; v1 += b1; v2 += b0; v3 += b1;
                v0 = (v0 > 20.0f) ? v0 : log1pf(__expf(v0));
                v1 = (v1 > 20.0f) ? v1 : log1pf(__expf(v1));
                v2 = (v2 > 20.0f) ? v2 : log1pf(__expf(v2));
                v3 = (v3 > 20.0f) ? v3 : log1pf(__expf(v3));
            }
            *(float2*)(C + (size_t)r0 * ldc + cc) = make_float2(v0, v1);
            *(float2*)(C + (size_t)(r0 + 8) * ldc + cc) = make_float2(v2, v3);
        }
    }
}

// ============================================================================
// conversion kernels (vectorized: 4 elems/thread)
// ============================================================================
__global__ void convert16_kernel(const float4* __restrict__ src,
                                 uint2* __restrict__ dst, int n4) {
    int i = blockIdx.x * blockDim.x + threadIdx.x;
    if (i >= n4) return;
    float4 v = src[i];
    uint2 o;
    o.x = pack2(v.x, v.y);
    o.y = pack2(v.z, v.w);
    dst[i] = o;
}

// W_dt [3072,96] -> fp16 [3072,128] zero-padded in K (4 elems/thread)
__global__ void convert_wdt_kernel(const float* __restrict__ src,
                                   uint2* __restrict__ dst) {
    int idx = blockIdx.x * blockDim.x + threadIdx.x;
    if (idx >= II * 32) return;
    int k4 = (idx & 31) * 4;
    int i = idx >> 5;
    float v[4];
#pragma unroll
    for (int t = 0; t < 4; t++)
        v[t] = (k4 + t < RR) ? src[i * RR + k4 + t] : 0.0f;
    uint2 o;
    o.x = pack2(v[0], v[1]);
    o.y = pack2(v[2], v[3]);
    dst[idx] = o;
}

// x_proj partial reduce + fp16 convert (4 elems/thread)
__global__ void reduce_ssmp_kernel() {
    int idx = blockIdx.x * blockDim.x + threadIdx.x;
    if (idx >= MTOT * PP / 4) return;
    const size_t s4 = (size_t)MTOT * PP / 4;
    const float4* p = (const float4*)g_part;
    float4 a = p[idx];
#pragma unroll
    for (int z = 1; z < SPLITK; z++) {
        float4 b = p[z * s4 + idx];
        a.x += b.x; a.y += b.y; a.z += b.z; a.w += b.w;
    }
    ((float4*)g_ssmp)[idx] = a;
    uint2 o; o.x = pack2(a.x, a.y); o.y = pack2(a.z, a.w);
    ((uint2*)g_sp16)[idx] = o;
}

// ============================================================================
// causal depthwise conv1d (K=4) + SiLU; 4 timesteps per thread
// ============================================================================
__global__ void conv_silu_kernel(const float* __restrict__ conv_w,
                                 const float* __restrict__ conv_b) {
    int idx = blockIdx.x * blockDim.x + threadIdx.x;
    if (idx >= (MTOT / 4) * II) return;
    const int i = idx % II;
    const int t = idx / II;
    const int m0 = t * 4;
    const int l0 = m0 & (LL - 1);

    float w0 = conv_w[i * 4 + 0], w1 = conv_w[i * 4 + 1];
    float w2 = conv_w[i * 4 + 2], w3 = conv_w[i * 4 + 3];
    const float cb = conv_b[i];

    float v[7];
#pragma unroll
    for (int j = 0; j < 7; j++) {
        int l = l0 - 3 + j;
        v[j] = (l >= 0) ? g_proj[(size_t)(m0 - 3 + j) * E2 + i] : 0.0f;
    }
#pragma unroll
    for (int s = 0; s < 4; s++) {
        float acc = fmaf(v[s], w0, fmaf(v[s + 1], w1, fmaf(v[s + 2], w2, fmaf(v[s + 3], w3, cb))));
        float o = acc / (1.0f + __expf(-acc));
        size_t off = (size_t)(m0 + s) * II + i;
        g_x[off] = o;
        g_x16[off] = __float2half(o);
    }
}

// ============================================================================
// Selective scan + D-skip + gate*silu(gate); all inputs staged via cp.async.
// ============================================================================
#define SCH 32
#define NCHUNK (LL / SCH)

__global__ __launch_bounds__(128)
void scan_kernel(const float* __restrict__ Amat, const float* __restrict__ Dvec) {
    __shared__ __align__(16) float sD[2][SCH * 32];
    __shared__ __align__(16) float sX[2][SCH * 32];
    __shared__ __align__(16) float sBC[2][SCH * 32];
    __shared__ __align__(16) float sG[2][SCH * 32];
    __shared__ __align__(16) float sY[SCH * 32];

    const int tid = threadIdx.x;
    const int blk = blockIdx.x;
    const int b = blk / 96;
    const int ibase = (blk % 96) * 32;
    const int q = tid & 3;
    const int c = tid >> 2;
    const int i = ibase + c;
    const int mbase = b * LL;

    float a2[4];
#pragma unroll
    for (int n = 0; n < 4; n++)
        a2[n] = Amat[i * NN + q * 4 + n] * 1.4426950408889634f;
    const float dv = Dvec[i];
    float st[4] = {0.0f, 0.0f, 0.0f, 0.0f};

    auto issue = [&](int buf, int ch) {
        const int m0 = mbase + ch * SCH;
#pragma unroll
        for (int k2 = 0; k2 < 2; k2++) {
            int f = tid + k2 * 128;
            int l = f >> 3;
            int c4 = (f & 7) * 4;
            int m = m0 + l;
            cp16(&sD[buf][l * 32 + c4], &g_delta[(size_t)m * II + ibase + c4]);
            cp16(&sX[buf][l * 32 + c4], &g_x[(size_t)m * II + ibase + c4]);
            cp16(&sBC[buf][l * 32 + c4], &g_ssmp[(size_t)m * PP + RR + c4]);
            cp16(&sG[buf][l * 32 + c4], &g_proj[(size_t)m * E2 + II + ibase + c4]);
        }
    };

    issue(0, 0);
    cp_commit();

    for (int ch = 0; ch < NCHUNK; ch++) {
        const int cur = ch & 1;
        if (ch + 1 < NCHUNK) {
            issue(1 - cur, ch + 1);
            cp_commit();
            cp_wait1();
        } else {
            cp_wait0();
        }
        __syncthreads();

        const int m0 = mbase + ch * SCH;
#pragma unroll 4
        for (int l = 0; l < SCH; l++) {
            const float delta = sD[cur][l * 32 + c];
            const float xv = sX[cur][l * 32 + c];
            const float du = delta * xv;
            const float4 Bv = *(const float4*)&sBC[cur][l * 32 + q * 4];
            const float4 Cv = *(const float4*)&sBC[cur][l * 32 + 16 + q * 4];
            float dA0 = fast_ex2(delta * a2[0]);
            float dA1 = fast_ex2(delta * a2[1]);
            float dA2 = fast_ex2(delta * a2[2]);
            float dA3 = fast_ex2(delta * a2[3]);
            st[0] = fmaf(st[0], dA0, du * Bv.x);
            st[1] = fmaf(st[1], dA1, du * Bv.y);
            st[2] = fmaf(st[2], dA2, du * Bv.z);
            st[3] = fmaf(st[3], dA3, du * Bv.w);
            float y = st[0] * Cv.x + st[1] * Cv.y + st[2] * Cv.z + st[3] * Cv.w;
            y += __shfl_xor_sync(0xffffffffu, y, 1);
            y += __shfl_xor_sync(0xffffffffu, y, 2);
            if (q == 0) {
                const float g = sG[cur][l * 32 + c];
                const float sg = g / (1.0f + __expf(-g));
                sY[l * 32 + c] = (y + xv * dv) * sg;
            }
        }
        __syncthreads();

#pragma unroll
        for (int k2 = 0; k2 < 4; k2++) {
            int f = tid + k2 * 128;
            int l = f >> 4;
            int c2 = (f & 15) * 2;
            __half2 p = __floats2half2_rn(sY[l * 32 + c2], sY[l * 32 + c2 + 1]);
            *(__half2*)&g_y16[(size_t)(m0 + l) * II + ibase + c2] = p;
        }
    }
}

// ============================================================================
// kernel_launch
// ============================================================================
extern "C" void kernel_launch(void* const* d_in, const int* in_sizes, int n_in,
                              void* d_out, int out_size) {
    const float* hs      = (const float*)d_in[0];
    const float* W_in    = (const float*)d_in[1];
    const float* conv_w  = (const float*)d_in[2];
    const float* conv_b  = (const float*)d_in[3];
    const float* W_x     = (const float*)d_in[4];
    const float* W_dt    = (const float*)d_in[5];
    const float* dt_bias = (const float*)d_in[6];
    const float* Amat    = (const float*)d_in[7];
    const float* Dvec    = (const float*)d_in[8];
    const float* W_out   = (const float*)d_in[9];
    float* out = (float*)d_out;

    float *proj, *delta, *part;
    cudaGetSymbolAddress((void**)&proj, g_proj);
    cudaGetSymbolAddress((void**)&delta, g_delta);
    cudaGetSymbolAddress((void**)&part, g_part);
    __half *hs16, *Win16, *x16, *Wx16, *sp16, *Wdt16, *y16, *Wout16;
    cudaGetSymbolAddress((void**)&hs16, g_hs16);
    cudaGetSymbolAddress((void**)&Win16, g_Win16);
    cudaGetSymbolAddress((void**)&x16, g_x16);
    cudaGetSymbolAddress((void**)&Wx16, g_Wx16);
    cudaGetSymbolAddress((void**)&sp16, g_sp16);
    cudaGetSymbolAddress((void**)&Wdt16, g_Wdt16);
    cudaGetSymbolAddress((void**)&y16, g_y16);
    cudaGetSymbolAddress((void**)&Wout16, g_Wout16);

    cudaFuncSetAttribute(gemm_mma<0>, cudaFuncAttributeMaxDynamicSharedMemorySize, GEMM_SMEM);
    cudaFuncSetAttribute(gemm_mma<1>, cudaFuncAttributeMaxDynamicSharedMemorySize, GEMM_SMEM);

    // conversions (vectorized)
    {
        int n4;
        n4 = MTOT * HH / 4;
        convert16_kernel<<<(n4 + 255) / 256, 256>>>((const float4*)hs, (uint2*)hs16, n4);
        n4 = E2 * HH / 4;
        convert16_kernel<<<(n4 + 255) / 256, 256>>>((const float4*)W_in, (uint2*)Win16, n4);
        n4 = PP * II / 4;
        convert16_kernel<<<(n4 + 255) / 256, 256>>>((const float4*)W_x, (uint2*)Wx16, n4);
        n4 = HH * II / 4;
        convert16_kernel<<<(n4 + 255) / 256, 256>>>((const float4*)W_out, (uint2*)Wout16, n4);
        n4 = II * 32;
        convert_wdt_kernel<<<(n4 + 255) / 256, 256>>>(W_dt, (uint2*)Wdt16);
    }

    // 1) in_proj: proj[4096,6144] = hs @ W_in^T  (K=1536)
    gemm_mma<0><<<dim3(E2 / 128, MTOT / 128, 1), 256, GEMM_SMEM>>>(
        hs16, Win16, HH, proj, E2, 0, nullptr);

    // 2) conv + SiLU
    {
        int total = (MTOT / 4) * II;
        conv_silu_kernel<<<(total + 255) / 256, 256>>>(conv_w, conv_b);
    }

    // 3) x_proj split-K(8): partials = x @ W_x^T  (K=3072)
    gemm_mma<0><<<dim3(1, MTOT / 128, SPLITK), 256, GEMM_SMEM>>>(
        x16, Wx16, II, part, PP, (size_t)MTOT * PP, nullptr);
    {
        int n4 = MTOT * PP / 4;
        reduce_ssmp_kernel<<<(n4 + 255) / 256, 256>>>();
    }

    // 4) dt_proj + softplus  (K=128 padded)
    gemm_mma<1><<<dim3(II / 128, MTOT / 128, 1), 256, GEMM_SMEM>>>(
        sp16, Wdt16, 128, delta, II, 0, dt_bias);

    // 5) scan -> y fp16
    scan_kernel<<<192, 128>>>(Amat, Dvec);

    // 6) out_proj: out[4096,1536] = y @ W_out^T  (K=3072)
    gemm_mma<0><<<dim3(HH / 128, MTOT / 128, 1), 256, GEMM_SMEM>>>(
        y16, Wout16, II, out, HH, 0, nullptr);
}